// round 7
// baseline (speedup 1.0000x reference)
#include <cuda_runtime.h>
#include <cstdint>
#include <cstdio>

#define NN 50000
#define NE 400000
#define HID 256
#define EDIM 768
#define NL 6

// ---------------- scratch (static device globals; no allocations) ----------------
__device__ float g_h0[NN * HID];        // ping
__device__ float g_h1[NN * HID];        // pong
__device__ float g_hl[NN * HID];        // per-layer h @ Wc
__device__ float g_ee[NL * NE];         // precomputed edge logits per layer
__device__ float g_ea[NE];              // alpha -> exp(alpha-max) in place
__device__ float g_s[NN];
__device__ float g_d[NN];
__device__ float g_mx[NN];
__device__ float g_dn[NN];
__device__ float g_Ve[NL * EDIM];       // We[l] @ a_e[l]
__device__ float g_W12[HID * HID];      // W1 @ W2
__device__ float g_Wsum[HID * HID];     // W3[:256] + W3[256:]

// ---------------- helpers ----------------
__device__ __forceinline__ void atomicMaxF(float* addr, float val) {
    if (val >= 0.f) atomicMax((int*)addr, __float_as_int(val));
    else            atomicMin((unsigned int*)addr, __float_as_uint(val));
}

// ---------------- 128x128x8 fp32 SGEMM, N=K=256 fixed ----------------
__global__ __launch_bounds__(256) void sgemm128(
    const float* __restrict__ A, const float* __restrict__ B,
    float* __restrict__ C, int M, int reluA)
{
    const int N = HID, K = HID;
    __shared__ float As[8][128];
    __shared__ float Bs[8][128];
    int tid = threadIdx.x;
    int bn = blockIdx.x * 128;
    int bm = blockIdx.y * 128;
    int arow = tid >> 1;
    int acol = (tid & 1) << 2;
    int brow = tid >> 5;
    int bcol = (tid & 31) << 2;
    int tx = tid & 15;
    int ty = tid >> 4;
    int grow = bm + arow;

    float acc[8][8];
#pragma unroll
    for (int i = 0; i < 8; i++)
#pragma unroll
        for (int j = 0; j < 8; j++) acc[i][j] = 0.f;

    for (int k0 = 0; k0 < K; k0 += 8) {
        float4 av = make_float4(0.f, 0.f, 0.f, 0.f);
        if (grow < M) av = *(const float4*)(A + (size_t)grow * K + k0 + acol);
        if (reluA) {
            av.x = fmaxf(av.x, 0.f); av.y = fmaxf(av.y, 0.f);
            av.z = fmaxf(av.z, 0.f); av.w = fmaxf(av.w, 0.f);
        }
        As[acol + 0][arow] = av.x;
        As[acol + 1][arow] = av.y;
        As[acol + 2][arow] = av.z;
        As[acol + 3][arow] = av.w;
        *(float4*)&Bs[brow][bcol] =
            *(const float4*)(B + (size_t)(k0 + brow) * N + bn + bcol);
        __syncthreads();
#pragma unroll
        for (int kk = 0; kk < 8; kk++) {
            float ra[8], rb[8];
            *(float4*)&ra[0] = *(const float4*)&As[kk][ty * 8];
            *(float4*)&ra[4] = *(const float4*)&As[kk][ty * 8 + 4];
            *(float4*)&rb[0] = *(const float4*)&Bs[kk][tx * 8];
            *(float4*)&rb[4] = *(const float4*)&Bs[kk][tx * 8 + 4];
#pragma unroll
            for (int i = 0; i < 8; i++)
#pragma unroll
                for (int j = 0; j < 8; j++)
                    acc[i][j] += ra[i] * rb[j];
        }
        __syncthreads();
    }
#pragma unroll
    for (int i = 0; i < 8; i++) {
        int r = bm + ty * 8 + i;
        if (r < M) {
            *(float4*)(C + (size_t)r * N + bn + tx * 8) =
                make_float4(acc[i][0], acc[i][1], acc[i][2], acc[i][3]);
            *(float4*)(C + (size_t)r * N + bn + tx * 8 + 4) =
                make_float4(acc[i][4], acc[i][5], acc[i][6], acc[i][7]);
        }
    }
}

// ---------------- small precompute kernels ----------------
__global__ void wsum_kernel(const float* __restrict__ W3, float* __restrict__ Wsum) {
    int i = blockIdx.x * blockDim.x + threadIdx.x;
    if (i < HID * HID) Wsum[i] = W3[i] + W3[i + HID * HID];
}

// Ve[l][j] = dot(We[l][j][:], a_e[l][:])  (one warp per (l,j))
__global__ void compute_Ve(const float* __restrict__ We, const float* __restrict__ a_e,
                           float* __restrict__ Ve) {
    int w = (blockIdx.x * blockDim.x + threadIdx.x) >> 5;
    int lane = threadIdx.x & 31;
    if (w >= NL * EDIM) return;
    int l = w / EDIM, j = w % EDIM;
    const float4* wr = (const float4*)(We + ((size_t)l * EDIM + j) * HID);
    const float4* ar = (const float4*)(a_e + (size_t)l * HID);
    float s = 0.f;
#pragma unroll
    for (int i = 0; i < 2; i++) {
        float4 x = wr[lane + 32 * i];
        float4 y = ar[lane + 32 * i];
        s += x.x * y.x + x.y * y.y + x.z * y.z + x.w * y.w;
    }
#pragma unroll
    for (int o = 16; o; o >>= 1) s += __shfl_xor_sync(~0u, s, o);
    if (!lane) Ve[l * EDIM + j] = s;
}

// edge_e[l][e] = dot(edge_attr[e], Ve[l])  — one warp per edge, all 6 layers at once
__global__ __launch_bounds__(256) void edge_dots(const float* __restrict__ edge_attr,
                                                 float* __restrict__ out) {
    __shared__ float4 sVe[NL][EDIM / 4];   // 18 KB
    for (int i = threadIdx.x; i < NL * EDIM / 4; i += blockDim.x)
        ((float4*)sVe)[i] = ((const float4*)g_Ve)[i];
    __syncthreads();
    int w = (blockIdx.x * blockDim.x + threadIdx.x) >> 5;
    int lane = threadIdx.x & 31;
    if (w >= NE) return;
    const float4* row = (const float4*)(edge_attr + (size_t)w * EDIM);
    float acc[NL] = {0.f, 0.f, 0.f, 0.f, 0.f, 0.f};
#pragma unroll
    for (int i = 0; i < 6; i++) {
        int p = lane + 32 * i;
        float4 v = row[p];
#pragma unroll
        for (int l = 0; l < NL; l++) {
            float4 u = sVe[l][p];
            acc[l] += v.x * u.x + v.y * u.y + v.z * u.z + v.w * u.w;
        }
    }
#pragma unroll
    for (int l = 0; l < NL; l++) {
        float a = acc[l];
#pragma unroll
        for (int o = 16; o; o >>= 1) a += __shfl_xor_sync(~0u, a, o);
        if (!lane) out[(size_t)l * NE + w] = a;
    }
}

// s[n]=dot(h[n],a_s); d[n]=dot(h[n],a_d)  — one warp per node
__global__ void node_dots(const float* __restrict__ h, const float* __restrict__ as_,
                          const float* __restrict__ ad_, float* __restrict__ s,
                          float* __restrict__ d) {
    int w = (blockIdx.x * blockDim.x + threadIdx.x) >> 5;
    int lane = threadIdx.x & 31;
    if (w >= NN) return;
    const float4* row = (const float4*)(h + (size_t)w * HID);
    const float4* A = (const float4*)as_;
    const float4* D = (const float4*)ad_;
    float ss = 0.f, dd = 0.f;
#pragma unroll
    for (int i = 0; i < 2; i++) {
        float4 v = row[lane + 32 * i];
        float4 a = A[lane + 32 * i];
        float4 b = D[lane + 32 * i];
        ss += v.x * a.x + v.y * a.y + v.z * a.z + v.w * a.w;
        dd += v.x * b.x + v.y * b.y + v.z * b.z + v.w * b.w;
    }
#pragma unroll
    for (int o = 16; o; o >>= 1) {
        ss += __shfl_xor_sync(~0u, ss, o);
        dd += __shfl_xor_sync(~0u, dd, o);
    }
    if (!lane) { s[w] = ss; d[w] = dd; }
}

__global__ void init_md(float* __restrict__ mx, float* __restrict__ dn) {
    int i = blockIdx.x * blockDim.x + threadIdx.x;
    if (i < NN) { mx[i] = -1e30f; dn[i] = 0.f; }
}

__global__ void zero_f4(float4* __restrict__ p, int n4) {
    int i = blockIdx.x * blockDim.x + threadIdx.x;
    if (i < n4) p[i] = make_float4(0.f, 0.f, 0.f, 0.f);
}

__global__ void alpha_max(const int* __restrict__ ei, const float* __restrict__ s,
                          const float* __restrict__ d, const float* __restrict__ ee,
                          float* __restrict__ alpha, float* __restrict__ mx) {
    int e = blockIdx.x * blockDim.x + threadIdx.x;
    if (e >= NE) return;
    int src = ei[e];
    int dst = ei[NE + e];
    float a = s[src] + d[dst] + ee[e];
    a = a > 0.f ? a : 0.2f * a;
    alpha[e] = a;
    atomicMaxF(&mx[dst], a);
}

__global__ void ea_den(const int* __restrict__ ei, float* __restrict__ alpha,
                       const float* __restrict__ mx, float* __restrict__ dn) {
    int e = blockIdx.x * blockDim.x + threadIdx.x;
    if (e >= NE) return;
    int dst = ei[NE + e];
    float v = expf(alpha[e] - mx[dst]);
    alpha[e] = v;
    atomicAdd(&dn[dst], v);
}

// out[dst] += h[src] * coef — one warp per edge, vectorized red.global.add.v4.f32
__global__ void scatter(const int* __restrict__ ei, const float* __restrict__ h,
                        const float* __restrict__ ea, const float* __restrict__ dn,
                        float* __restrict__ out) {
    int w = (blockIdx.x * blockDim.x + threadIdx.x) >> 5;
    int lane = threadIdx.x & 31;
    if (w >= NE) return;
    int src = ei[w];
    int dst = ei[NE + w];
    float coef = ea[w] / (dn[dst] + 1e-16f);
    const float4* hs = (const float4*)(h + (size_t)src * HID);
    float* ob = out + (size_t)dst * HID;
#pragma unroll
    for (int i = 0; i < 2; i++) {
        int p = lane + 32 * i;
        float4 v = hs[p];
        float x = v.x * coef, y = v.y * coef, z = v.z * coef, u = v.w * coef;
        asm volatile("red.global.add.v4.f32 [%0], {%1,%2,%3,%4};"
                     :: "l"(ob + p * 4), "f"(x), "f"(y), "f"(z), "f"(u)
                     : "memory");
    }
}

__global__ void bias_add(float* __restrict__ h, const float* __restrict__ b) {
    int i = blockIdx.x * blockDim.x + threadIdx.x;
    if (i >= NN * HID / 4) return;
    float4 v = ((float4*)h)[i];
    float4 bb = ((const float4*)b)[i & 63];
    v.x += bb.x; v.y += bb.y; v.z += bb.z; v.w += bb.w;
    ((float4*)h)[i] = v;
}

// ---------------- launch ----------------
extern "C" void kernel_launch(void* const* d_in, const int* in_sizes, int n_in,
                              void* d_out, int out_size) {
    const float* x    = (const float*)d_in[0];
    const int*   ei   = (const int*)d_in[1];      // int32 (jax x64 disabled)
    const float* eatt = (const float*)d_in[2];
    const float* W1   = (const float*)d_in[3];
    const float* W2   = (const float*)d_in[4];
    const float* Wc   = (const float*)d_in[5];
    const float* We   = (const float*)d_in[6];
    const float* a_s  = (const float*)d_in[7];
    const float* a_d  = (const float*)d_in[8];
    const float* a_e  = (const float*)d_in[9];
    const float* bias = (const float*)d_in[10];
    const float* W3   = (const float*)d_in[11];
    float*       out  = (float*)d_out;

    float *p_h0, *p_h1, *p_hl, *p_ee, *p_ea, *p_s, *p_d, *p_mx, *p_dn, *p_Ve, *p_W12, *p_Ws;
    cudaGetSymbolAddress((void**)&p_h0, g_h0);
    cudaGetSymbolAddress((void**)&p_h1, g_h1);
    cudaGetSymbolAddress((void**)&p_hl, g_hl);
    cudaGetSymbolAddress((void**)&p_ee, g_ee);
    cudaGetSymbolAddress((void**)&p_ea, g_ea);
    cudaGetSymbolAddress((void**)&p_s, g_s);
    cudaGetSymbolAddress((void**)&p_d, g_d);
    cudaGetSymbolAddress((void**)&p_mx, g_mx);
    cudaGetSymbolAddress((void**)&p_dn, g_dn);
    cudaGetSymbolAddress((void**)&p_Ve, g_Ve);
    cudaGetSymbolAddress((void**)&p_W12, g_W12);
    cudaGetSymbolAddress((void**)&p_Ws, g_Wsum);

    const int MB = (NN + 127) / 128;

    // precompute: W12 = W1@W2, Wsum = W3a+W3b, Ve, edge logits (all 6 layers)
    sgemm128<<<dim3(2, 2), 256>>>(W1, W2, p_W12, HID, 0);
    wsum_kernel<<<(HID * HID + 255) / 256, 256>>>(W3, p_Ws);
    compute_Ve<<<(NL * EDIM * 32 + 255) / 256, 256>>>(We, a_e, p_Ve);
    edge_dots<<<(NE * 32 + 255) / 256, 256>>>(eatt, p_ee);

    // h0 = x @ W12
    sgemm128<<<dim3(2, MB), 256>>>(x, p_W12, p_h0, NN, 0);

    float* hcur = p_h0;
    float* hnext = p_h1;
    for (int l = 0; l < NL; l++) {
        sgemm128<<<dim3(2, MB), 256>>>(hcur, Wc + (size_t)l * HID * HID, p_hl, NN, 0);
        node_dots<<<(NN * 32 + 255) / 256, 256>>>(p_hl, a_s + l * HID, a_d + l * HID,
                                                  p_s, p_d);
        init_md<<<(NN + 255) / 256, 256>>>(p_mx, p_dn);
        zero_f4<<<(NN * HID / 4 + 255) / 256, 256>>>((float4*)hnext, NN * HID / 4);
        alpha_max<<<(NE + 255) / 256, 256>>>(ei, p_s, p_d, p_ee + (size_t)l * NE,
                                             p_ea, p_mx);
        ea_den<<<(NE + 255) / 256, 256>>>(ei, p_ea, p_mx, p_dn);
        scatter<<<(NE * 32 + 255) / 256, 256>>>(ei, p_hl, p_ea, p_dn, hnext);
        bias_add<<<(NN * HID / 4 + 255) / 256, 256>>>(hnext, bias + l * HID);
        float* t = hcur; hcur = hnext; hnext = t;
    }

    // out = relu(h) @ (W3a + W3b)
    sgemm128<<<dim3(2, MB), 256>>>(hcur, p_Ws, out, NN, 1);
}